// round 1
// baseline (speedup 1.0000x reference)
#include <cuda_runtime.h>
#include <math.h>

#define BATCH 2
#define SEQ   2048
#define DMODEL 1024
#define HEADS 16
#define HD    64
#define QKV_N (3*DMODEL)       // 3072
#define MROWS (BATCH*SEQ)      // 4096

// scratch (allocations are forbidden; __device__ globals are the sanctioned path)
__device__ float g_qkv[(size_t)MROWS * QKV_N];   // [B*S, 3072] ; n = h*192 + part*64 + d
__device__ float g_att[(size_t)MROWS * DMODEL];  // [B*S, 1024] ; col = h*64 + d

// ---------------------------------------------------------------------------
// Generic tiled GEMM + bias:  C[M,N] = A[M,K] @ W[K,N] + bias[N]
// BM=BN=64, BK=16, 256 threads, 4x4 micro-tile per thread.
// ---------------------------------------------------------------------------
__global__ __launch_bounds__(256)
void gemm_bias_kernel(const float* __restrict__ A, const float* __restrict__ W,
                      const float* __restrict__ bias, float* __restrict__ C,
                      int M, int N, int K)
{
    __shared__ float As[64][17];   // [row][k], pad to kill cross-group conflicts
    __shared__ float Bs[16][64];   // [k][col], col read pattern tc+16*i is conflict-free

    const int t  = threadIdx.x;
    const int tr = t >> 4;         // 0..15 -> rows tr*4..tr*4+3
    const int tc = t & 15;         // 0..15 -> cols tc+16*i
    const int m0 = blockIdx.y * 64;
    const int n0 = blockIdx.x * 64;

    float acc[4][4];
#pragma unroll
    for (int a = 0; a < 4; a++)
#pragma unroll
        for (int b = 0; b < 4; b++) acc[a][b] = 0.f;

    const int a_row = t >> 2;            // 64 rows
    const int a_seg = (t & 3) << 2;      // 4 float4 per row
    const int b_row = t >> 4;            // 16 rows
    const int b_seg = (t & 15) << 2;     // 16 float4 per row

    for (int k0 = 0; k0 < K; k0 += 16) {
        float4 av = *(const float4*)(A + (size_t)(m0 + a_row) * K + k0 + a_seg);
        As[a_row][a_seg + 0] = av.x;
        As[a_row][a_seg + 1] = av.y;
        As[a_row][a_seg + 2] = av.z;
        As[a_row][a_seg + 3] = av.w;
        float4 bv = *(const float4*)(W + (size_t)(k0 + b_row) * N + n0 + b_seg);
        *(float4*)&Bs[b_row][b_seg] = bv;
        __syncthreads();

#pragma unroll
        for (int kk = 0; kk < 16; kk++) {
            float ar[4], bc[4];
#pragma unroll
            for (int ii = 0; ii < 4; ii++) ar[ii] = As[tr * 4 + ii][kk];
#pragma unroll
            for (int i = 0; i < 4; i++)    bc[i]  = Bs[kk][tc + 16 * i];
#pragma unroll
            for (int ii = 0; ii < 4; ii++)
#pragma unroll
                for (int i = 0; i < 4; i++)
                    acc[ii][i] = fmaf(ar[ii], bc[i], acc[ii][i]);
        }
        __syncthreads();
    }

#pragma unroll
    for (int i = 0; i < 4; i++) {
        int c = n0 + tc + 16 * i;
        float bb = bias[c];
#pragma unroll
        for (int ii = 0; ii < 4; ii++)
            C[(size_t)(m0 + tr * 4 + ii) * N + c] = acc[ii][i] + bb;
    }
}

// ---------------------------------------------------------------------------
// Flash attention: per (b,h), 64-query blocks, online softmax over 64-key tiles.
// Reads Q/K/V directly from the packed qkv buffer.
// ---------------------------------------------------------------------------
#define AP 65                      // smem row pitch (floats)
#define ATT_SMEM (4 * 64 * AP * sizeof(float))   // 66,560 B

__global__ __launch_bounds__(256)
void attn_kernel(const float* __restrict__ qkv, const float* __restrict__ mask,
                 float* __restrict__ att)
{
    extern __shared__ float sm[];
    float* Qs = sm;                 // [64][AP]
    float* Ks = sm + 64 * AP;
    float* Vs = sm + 2 * 64 * AP;
    float* Ps = sm + 3 * 64 * AP;

    const int t  = threadIdx.x;
    const int tr = t >> 4;
    const int tc = t & 15;
    const int bh = blockIdx.y;
    const int b  = bh / HEADS;
    const int h  = bh % HEADS;
    const int q0 = blockIdx.x * 64;

    const float* qbase = qkv + ((size_t)(b * SEQ + q0)) * QKV_N + h * (3 * HD);

    // load Q tile [64][64]
    for (int i = t; i < 64 * 16; i += 256) {
        int row = i >> 4, seg = (i & 15) << 2;
        float4 v = *(const float4*)(qbase + (size_t)row * QKV_N + seg);
        Qs[row * AP + seg + 0] = v.x;
        Qs[row * AP + seg + 1] = v.y;
        Qs[row * AP + seg + 2] = v.z;
        Qs[row * AP + seg + 3] = v.w;
    }

    float m[4], l[4], acc[4][4];
#pragma unroll
    for (int ii = 0; ii < 4; ii++) {
        m[ii] = -1e30f; l[ii] = 0.f;
#pragma unroll
        for (int i = 0; i < 4; i++) acc[ii][i] = 0.f;
    }

    for (int j = 0; j < SEQ / 64; j++) {
        const int k0g = j * 64;
        __syncthreads();   // protect Ks/Vs/Ps from previous iteration's readers

        const float* kbase = qkv + ((size_t)(b * SEQ + k0g)) * QKV_N + h * (3 * HD) + HD;
        const float* vbase = kbase + HD;
        for (int i = t; i < 64 * 16; i += 256) {
            int row = i >> 4, seg = (i & 15) << 2;
            float4 kv = *(const float4*)(kbase + (size_t)row * QKV_N + seg);
            Ks[row * AP + seg + 0] = kv.x;
            Ks[row * AP + seg + 1] = kv.y;
            Ks[row * AP + seg + 2] = kv.z;
            Ks[row * AP + seg + 3] = kv.w;
            float4 vv = *(const float4*)(vbase + (size_t)row * QKV_N + seg);
            Vs[row * AP + seg + 0] = vv.x;
            Vs[row * AP + seg + 1] = vv.y;
            Vs[row * AP + seg + 2] = vv.z;
            Vs[row * AP + seg + 3] = vv.w;
        }
        __syncthreads();

        // scores s[4][4] = Q[r]·K[c]
        float s[4][4];
#pragma unroll
        for (int ii = 0; ii < 4; ii++)
#pragma unroll
            for (int i = 0; i < 4; i++) s[ii][i] = 0.f;

#pragma unroll 8
        for (int d = 0; d < 64; d++) {
            float qr[4], kc[4];
#pragma unroll
            for (int ii = 0; ii < 4; ii++) qr[ii] = Qs[(tr * 4 + ii) * AP + d];
#pragma unroll
            for (int i = 0; i < 4; i++)    kc[i]  = Ks[(tc + 16 * i) * AP + d];
#pragma unroll
            for (int ii = 0; ii < 4; ii++)
#pragma unroll
                for (int i = 0; i < 4; i++)
                    s[ii][i] = fmaf(qr[ii], kc[i], s[ii][i]);
        }

        // scale + additive mask
#pragma unroll
        for (int ii = 0; ii < 4; ii++) {
            const float* mrow = mask + (size_t)(q0 + tr * 4 + ii) * SEQ + k0g;
#pragma unroll
            for (int i = 0; i < 4; i++)
                s[ii][i] = s[ii][i] * 0.125f + mrow[tc + 16 * i];
        }

        // online softmax (row groups = 16 consecutive lanes)
#pragma unroll
        for (int ii = 0; ii < 4; ii++) {
            float mx = fmaxf(fmaxf(s[ii][0], s[ii][1]), fmaxf(s[ii][2], s[ii][3]));
#pragma unroll
            for (int off = 8; off >= 1; off >>= 1)
                mx = fmaxf(mx, __shfl_xor_sync(0xffffffffu, mx, off));
            float mnew = fmaxf(m[ii], mx);
            float corr = __expf(m[ii] - mnew);
            float rsum = 0.f;
#pragma unroll
            for (int i = 0; i < 4; i++) {
                float p = __expf(s[ii][i] - mnew);
                Ps[(tr * 4 + ii) * AP + tc + 16 * i] = p;
                rsum += p;
            }
#pragma unroll
            for (int off = 8; off >= 1; off >>= 1)
                rsum += __shfl_xor_sync(0xffffffffu, rsum, off);
            l[ii] = l[ii] * corr + rsum;
            m[ii] = mnew;
#pragma unroll
            for (int i = 0; i < 4; i++) acc[ii][i] *= corr;
        }
        __syncthreads();

        // acc += P @ V
#pragma unroll 8
        for (int c = 0; c < 64; c++) {
            float pr[4], vc[4];
#pragma unroll
            for (int ii = 0; ii < 4; ii++) pr[ii] = Ps[(tr * 4 + ii) * AP + c];
#pragma unroll
            for (int i = 0; i < 4; i++)    vc[i]  = Vs[c * AP + tc + 16 * i];
#pragma unroll
            for (int ii = 0; ii < 4; ii++)
#pragma unroll
                for (int i = 0; i < 4; i++)
                    acc[ii][i] = fmaf(pr[ii], vc[i], acc[ii][i]);
        }
    }

    // normalize + write (att layout: [b*S+q][h*64+d])
#pragma unroll
    for (int ii = 0; ii < 4; ii++) {
        float inv = 1.f / l[ii];
        size_t rowoff = (size_t)(b * SEQ + q0 + tr * 4 + ii) * DMODEL + h * HD;
#pragma unroll
        for (int i = 0; i < 4; i++)
            att[rowoff + tc + 16 * i] = acc[ii][i] * inv;
    }
}

// ---------------------------------------------------------------------------
extern "C" void kernel_launch(void* const* d_in, const int* in_sizes, int n_in,
                              void* d_out, int out_size)
{
    const float* x     = (const float*)d_in[0];   // [B,S,D]
    const float* mask  = (const float*)d_in[1];   // [S,S]
    const float* w_qkv = (const float*)d_in[2];   // [D,3D]
    const float* b_qkv = (const float*)d_in[3];   // [3D]
    const float* w_out = (const float*)d_in[4];   // [D,D]
    const float* b_out = (const float*)d_in[5];   // [D]
    float* out = (float*)d_out;                   // [B,S,D]

    float* qkv; cudaGetSymbolAddress((void**)&qkv, g_qkv);
    float* att; cudaGetSymbolAddress((void**)&att, g_att);

    // 1) QKV projection: [4096,1024] @ [1024,3072] + b
    {
        dim3 grid(QKV_N / 64, MROWS / 64);
        gemm_bias_kernel<<<grid, 256>>>(x, w_qkv, b_qkv, qkv, MROWS, QKV_N, DMODEL);
    }

    // 2) attention
    {
        cudaFuncSetAttribute(attn_kernel, cudaFuncAttributeMaxDynamicSharedMemorySize,
                             (int)ATT_SMEM);
        dim3 grid(SEQ / 64, BATCH * HEADS);
        attn_kernel<<<grid, 256, ATT_SMEM>>>(qkv, mask, att);
    }

    // 3) output projection: [4096,1024] @ [1024,1024] + b
    {
        dim3 grid(DMODEL / 64, MROWS / 64);
        gemm_bias_kernel<<<grid, 256>>>(att, w_out, b_out, out, MROWS, DMODEL, DMODEL);
    }
}

// round 3
// speedup vs baseline: 1.3852x; 1.3852x over previous
#include <cuda_runtime.h>
#include <math.h>
#include <stdint.h>

#define BATCH 2
#define SEQ   2048
#define DMODEL 1024
#define HEADS 16
#define HD    64
#define QKV_N (3*DMODEL)       // 3072
#define MROWS (BATCH*SEQ)      // 4096

// scratch (allocations are forbidden; __device__ globals are the sanctioned path)
__device__ float g_qkv[(size_t)MROWS * QKV_N];    // [B*S, 3072]
__device__ float g_att[(size_t)MROWS * DMODEL];   // [B*S, 1024]

// ===========================================================================
// helpers
// ===========================================================================
__device__ __forceinline__ float f2tf32(float f) {
    uint32_t r;
    asm("cvt.rna.tf32.f32 %0, %1;" : "=r"(r) : "f"(f));
    return __uint_as_float(r);
}

__device__ __forceinline__ void mma_tf32(float c[4], const uint32_t a[4], const uint32_t b[2]) {
    asm volatile(
        "mma.sync.aligned.m16n8k8.row.col.f32.tf32.tf32.f32 "
        "{%0,%1,%2,%3}, {%4,%5,%6,%7}, {%8,%9}, {%0,%1,%2,%3};"
        : "+f"(c[0]), "+f"(c[1]), "+f"(c[2]), "+f"(c[3])
        : "r"(a[0]), "r"(a[1]), "r"(a[2]), "r"(a[3]), "r"(b[0]), "r"(b[1]));
}

// ===========================================================================
// tf32 mma.sync GEMM + bias:  C[M,N] = A[M,K] @ W[K,N] + bias[N]
// CTA 128x128, BK=16, 8 warps (each 64x32), reg-staged double buffer.
// Smem: As pitch 20 floats, Bs pitch 136 floats (both conflict-free for
// the m16n8k8 fragment access pattern).
// ===========================================================================
#define AS_P 20
#define BS_P 136
#define AS_FLOATS (128 * AS_P)          // 2560
#define BS_FLOATS (16 * BS_P)           // 2176
#define GEMM_SMEM ((2 * AS_FLOATS + 2 * BS_FLOATS) * sizeof(float))  // 37888

__global__ __launch_bounds__(256)
void gemm_mma_kernel(const float* __restrict__ A, const float* __restrict__ W,
                     const float* __restrict__ bias, float* __restrict__ C,
                     int N, int K)
{
    extern __shared__ float smf[];
    float* As[2] = { smf, smf + AS_FLOATS };
    float* Bs[2] = { smf + 2 * AS_FLOATS, smf + 2 * AS_FLOATS + BS_FLOATS };

    const int t    = threadIdx.x;
    const int lane = t & 31;
    const int wid  = t >> 5;
    const int wm   = (wid >> 2) * 64;   // warp M offset in tile
    const int wn   = (wid & 3) * 32;    // warp N offset in tile
    const int g    = lane >> 2;         // group id (0..7)
    const int t4   = lane & 3;          // thread in group
    const int m0   = blockIdx.y * 128;
    const int n0   = blockIdx.x * 128;

    float acc[4][4][4];
#pragma unroll
    for (int mi = 0; mi < 4; mi++)
#pragma unroll
        for (int ni = 0; ni < 4; ni++)
#pragma unroll
            for (int r = 0; r < 4; r++) acc[mi][ni][r] = 0.f;

    const int nch = K / 16;

    // prologue: chunk 0 -> buffer 0
    {
        const float* Ab = A + (size_t)m0 * K;
        const float* Wb = W + n0;
#pragma unroll
        for (int i = 0; i < 2; i++) {
            int idx = t + i * 256;
            int ar = idx >> 2, as = idx & 3;
            float4 v = *(const float4*)(Ab + (size_t)ar * K + as * 4);
            float* d = As[0] + ar * AS_P + as * 4;
            d[0] = f2tf32(v.x); d[1] = f2tf32(v.y); d[2] = f2tf32(v.z); d[3] = f2tf32(v.w);
            int br = idx >> 5, bs = idx & 31;
            float4 w = *(const float4*)(Wb + (size_t)br * N + bs * 4);
            float* e = Bs[0] + br * BS_P + bs * 4;
            e[0] = f2tf32(w.x); e[1] = f2tf32(w.y); e[2] = f2tf32(w.z); e[3] = f2tf32(w.w);
        }
    }
    __syncthreads();

    for (int ch = 0; ch < nch; ch++) {
        const int s = ch & 1;

        // prefetch next chunk into registers
        float4 ra[2], rb[2];
        if (ch + 1 < nch) {
            const float* Ab = A + (size_t)m0 * K + (ch + 1) * 16;
            const float* Wb = W + (size_t)(ch + 1) * 16 * N + n0;
#pragma unroll
            for (int i = 0; i < 2; i++) {
                int idx = t + i * 256;
                ra[i] = *(const float4*)(Ab + (size_t)(idx >> 2) * K + (idx & 3) * 4);
                rb[i] = *(const float4*)(Wb + (size_t)(idx >> 5) * N + (idx & 31) * 4);
            }
        }

        // compute: 2 k-steps of 8
        const float* as_ = As[s];
        const float* bs_ = Bs[s];
#pragma unroll
        for (int ks = 0; ks < 2; ks++) {
            const int kk = ks * 8;
            uint32_t af[4][4], bf[4][2];
#pragma unroll
            for (int mi = 0; mi < 4; mi++) {
                int r0 = wm + mi * 16 + g;
                af[mi][0] = __float_as_uint(as_[r0 * AS_P + kk + t4]);
                af[mi][1] = __float_as_uint(as_[(r0 + 8) * AS_P + kk + t4]);
                af[mi][2] = __float_as_uint(as_[r0 * AS_P + kk + t4 + 4]);
                af[mi][3] = __float_as_uint(as_[(r0 + 8) * AS_P + kk + t4 + 4]);
            }
#pragma unroll
            for (int ni = 0; ni < 4; ni++) {
                int cc = wn + ni * 8 + g;
                bf[ni][0] = __float_as_uint(bs_[(kk + t4) * BS_P + cc]);
                bf[ni][1] = __float_as_uint(bs_[(kk + t4 + 4) * BS_P + cc]);
            }
#pragma unroll
            for (int mi = 0; mi < 4; mi++)
#pragma unroll
                for (int ni = 0; ni < 4; ni++)
                    mma_tf32(acc[mi][ni], af[mi], bf[ni]);
        }

        if (ch + 1 < nch) {
            __syncthreads();
            const int sn = s ^ 1;
#pragma unroll
            for (int i = 0; i < 2; i++) {
                int idx = t + i * 256;
                int ar = idx >> 2, as = idx & 3;
                float* d = As[sn] + ar * AS_P + as * 4;
                d[0] = f2tf32(ra[i].x); d[1] = f2tf32(ra[i].y);
                d[2] = f2tf32(ra[i].z); d[3] = f2tf32(ra[i].w);
                int br = idx >> 5, bs = idx & 31;
                float* e = Bs[sn] + br * BS_P + bs * 4;
                e[0] = f2tf32(rb[i].x); e[1] = f2tf32(rb[i].y);
                e[2] = f2tf32(rb[i].z); e[3] = f2tf32(rb[i].w);
            }
            __syncthreads();
        }
    }

    // epilogue: fragments -> gmem with bias (c0,c1 are adjacent columns)
#pragma unroll
    for (int mi = 0; mi < 4; mi++) {
        int row = m0 + wm + mi * 16 + g;
#pragma unroll
        for (int ni = 0; ni < 4; ni++) {
            int col = n0 + wn + ni * 8 + 2 * t4;
            float2 bv = *(const float2*)(bias + col);
            float2 v0 = make_float2(acc[mi][ni][0] + bv.x, acc[mi][ni][1] + bv.y);
            float2 v1 = make_float2(acc[mi][ni][2] + bv.x, acc[mi][ni][3] + bv.y);
            *(float2*)(C + (size_t)row * N + col)       = v0;
            *(float2*)(C + (size_t)(row + 8) * N + col) = v1;
        }
    }
}

// ---------------------------------------------------------------------------
// Flash attention (unchanged, known-good from R1): per (b,h), 64-query blocks.
// ---------------------------------------------------------------------------
#define AP 65
#define ATT_SMEM (4 * 64 * AP * sizeof(float))

__global__ __launch_bounds__(256)
void attn_kernel(const float* __restrict__ qkv, const float* __restrict__ mask,
                 float* __restrict__ att)
{
    extern __shared__ float smf[];
    float* Qs = smf;
    float* Ks = smf + 64 * AP;
    float* Vs = smf + 2 * 64 * AP;
    float* Ps = smf + 3 * 64 * AP;

    const int t  = threadIdx.x;
    const int tr = t >> 4;
    const int tc = t & 15;
    const int bh = blockIdx.y;
    const int b  = bh / HEADS;
    const int h  = bh % HEADS;
    const int q0 = blockIdx.x * 64;

    const float* qbase = qkv + ((size_t)(b * SEQ + q0)) * QKV_N + h * (3 * HD);

    for (int i = t; i < 64 * 16; i += 256) {
        int row = i >> 4, seg = (i & 15) << 2;
        float4 v = *(const float4*)(qbase + (size_t)row * QKV_N + seg);
        Qs[row * AP + seg + 0] = v.x;
        Qs[row * AP + seg + 1] = v.y;
        Qs[row * AP + seg + 2] = v.z;
        Qs[row * AP + seg + 3] = v.w;
    }

    float m[4], l[4], acc[4][4];
#pragma unroll
    for (int ii = 0; ii < 4; ii++) {
        m[ii] = -1e30f; l[ii] = 0.f;
#pragma unroll
        for (int i = 0; i < 4; i++) acc[ii][i] = 0.f;
    }

    for (int j = 0; j < SEQ / 64; j++) {
        const int k0g = j * 64;
        __syncthreads();

        const float* kbase = qkv + ((size_t)(b * SEQ + k0g)) * QKV_N + h * (3 * HD) + HD;
        const float* vbase = kbase + HD;
        for (int i = t; i < 64 * 16; i += 256) {
            int row = i >> 4, seg = (i & 15) << 2;
            float4 kv = *(const float4*)(kbase + (size_t)row * QKV_N + seg);
            Ks[row * AP + seg + 0] = kv.x;
            Ks[row * AP + seg + 1] = kv.y;
            Ks[row * AP + seg + 2] = kv.z;
            Ks[row * AP + seg + 3] = kv.w;
            float4 vv = *(const float4*)(vbase + (size_t)row * QKV_N + seg);
            Vs[row * AP + seg + 0] = vv.x;
            Vs[row * AP + seg + 1] = vv.y;
            Vs[row * AP + seg + 2] = vv.z;
            Vs[row * AP + seg + 3] = vv.w;
        }
        __syncthreads();

        float s[4][4];
#pragma unroll
        for (int ii = 0; ii < 4; ii++)
#pragma unroll
            for (int i = 0; i < 4; i++) s[ii][i] = 0.f;

#pragma unroll 8
        for (int d = 0; d < 64; d++) {
            float qr[4], kc[4];
#pragma unroll
            for (int ii = 0; ii < 4; ii++) qr[ii] = Qs[(tr * 4 + ii) * AP + d];
#pragma unroll
            for (int i = 0; i < 4; i++)    kc[i]  = Ks[(tc + 16 * i) * AP + d];
#pragma unroll
            for (int ii = 0; ii < 4; ii++)
#pragma unroll
                for (int i = 0; i < 4; i++)
                    s[ii][i] = fmaf(qr[ii], kc[i], s[ii][i]);
        }

#pragma unroll
        for (int ii = 0; ii < 4; ii++) {
            const float* mrow = mask + (size_t)(q0 + tr * 4 + ii) * SEQ + k0g;
#pragma unroll
            for (int i = 0; i < 4; i++)
                s[ii][i] = s[ii][i] * 0.125f + mrow[tc + 16 * i];
        }

#pragma unroll
        for (int ii = 0; ii < 4; ii++) {
            float mx = fmaxf(fmaxf(s[ii][0], s[ii][1]), fmaxf(s[ii][2], s[ii][3]));
#pragma unroll
            for (int off = 8; off >= 1; off >>= 1)
                mx = fmaxf(mx, __shfl_xor_sync(0xffffffffu, mx, off));
            float mnew = fmaxf(m[ii], mx);
            float corr = __expf(m[ii] - mnew);
            float rsum = 0.f;
#pragma unroll
            for (int i = 0; i < 4; i++) {
                float p = __expf(s[ii][i] - mnew);
                Ps[(tr * 4 + ii) * AP + tc + 16 * i] = p;
                rsum += p;
            }
#pragma unroll
            for (int off = 8; off >= 1; off >>= 1)
                rsum += __shfl_xor_sync(0xffffffffu, rsum, off);
            l[ii] = l[ii] * corr + rsum;
            m[ii] = mnew;
#pragma unroll
            for (int i = 0; i < 4; i++) acc[ii][i] *= corr;
        }
        __syncthreads();

#pragma unroll 8
        for (int c = 0; c < 64; c++) {
            float pr[4], vc[4];
#pragma unroll
            for (int ii = 0; ii < 4; ii++) pr[ii] = Ps[(tr * 4 + ii) * AP + c];
#pragma unroll
            for (int i = 0; i < 4; i++)    vc[i]  = Vs[c * AP + tc + 16 * i];
#pragma unroll
            for (int ii = 0; ii < 4; ii++)
#pragma unroll
                for (int i = 0; i < 4; i++)
                    acc[ii][i] = fmaf(pr[ii], vc[i], acc[ii][i]);
        }
    }

#pragma unroll
    for (int ii = 0; ii < 4; ii++) {
        float inv = 1.f / l[ii];
        size_t rowoff = (size_t)(b * SEQ + q0 + tr * 4 + ii) * DMODEL + h * HD;
#pragma unroll
        for (int i = 0; i < 4; i++)
            att[rowoff + tc + 16 * i] = acc[ii][i] * inv;
    }
}

// ---------------------------------------------------------------------------
extern "C" void kernel_launch(void* const* d_in, const int* in_sizes, int n_in,
                              void* d_out, int out_size)
{
    const float* x     = (const float*)d_in[0];
    const float* mask  = (const float*)d_in[1];
    const float* w_qkv = (const float*)d_in[2];
    const float* b_qkv = (const float*)d_in[3];
    const float* w_out = (const float*)d_in[4];
    const float* b_out = (const float*)d_in[5];
    float* out = (float*)d_out;

    float* qkv; cudaGetSymbolAddress((void**)&qkv, g_qkv);
    float* att; cudaGetSymbolAddress((void**)&att, g_att);

    cudaFuncSetAttribute(gemm_mma_kernel, cudaFuncAttributeMaxDynamicSharedMemorySize,
                         (int)GEMM_SMEM);
    cudaFuncSetAttribute(attn_kernel, cudaFuncAttributeMaxDynamicSharedMemorySize,
                         (int)ATT_SMEM);

    // 1) QKV projection: [4096,1024] @ [1024,3072] + b  (tf32 mma.sync)
    {
        dim3 grid(QKV_N / 128, MROWS / 128);
        gemm_mma_kernel<<<grid, 256, GEMM_SMEM>>>(x, w_qkv, b_qkv, qkv, QKV_N, DMODEL);
    }

    // 2) attention (fp32 SIMT, unchanged)
    {
        dim3 grid(SEQ / 64, BATCH * HEADS);
        attn_kernel<<<grid, 256, ATT_SMEM>>>(qkv, mask, att);
    }

    // 3) output projection: [4096,1024] @ [1024,1024] + b  (tf32 mma.sync)
    {
        dim3 grid(DMODEL / 128, MROWS / 128);
        gemm_mma_kernel<<<grid, 256, GEMM_SMEM>>>(att, w_out, b_out, out, DMODEL, DMODEL);
    }
}

// round 4
// speedup vs baseline: 2.3718x; 1.7122x over previous
#include <cuda_runtime.h>
#include <math.h>
#include <stdint.h>

#define BATCH 2
#define SEQ   2048
#define DMODEL 1024
#define HEADS 16
#define HD    64
#define QKV_N (3*DMODEL)       // 3072
#define MROWS (BATCH*SEQ)      // 4096

__device__ float g_qkv[(size_t)MROWS * QKV_N];    // [B*S, 3072]
__device__ float g_att[(size_t)MROWS * DMODEL];   // [B*S, 1024]

// ===========================================================================
// helpers
// ===========================================================================
__device__ __forceinline__ float f2tf32(float f) {
    uint32_t r;
    asm("cvt.rna.tf32.f32 %0, %1;" : "=r"(r) : "f"(f));
    return __uint_as_float(r);
}

__device__ __forceinline__ void mma_tf32(float c[4], const uint32_t a[4], const uint32_t b[2]) {
    asm volatile(
        "mma.sync.aligned.m16n8k8.row.col.f32.tf32.tf32.f32 "
        "{%0,%1,%2,%3}, {%4,%5,%6,%7}, {%8,%9}, {%0,%1,%2,%3};"
        : "+f"(c[0]), "+f"(c[1]), "+f"(c[2]), "+f"(c[3])
        : "r"(a[0]), "r"(a[1]), "r"(a[2]), "r"(a[3]), "r"(b[0]), "r"(b[1]));
}

// ===========================================================================
// tf32 mma.sync GEMM + bias (unchanged from R3 — passing)
// ===========================================================================
#define AS_P 20
#define BS_P 136
#define AS_FLOATS (128 * AS_P)
#define BS_FLOATS (16 * BS_P)
#define GEMM_SMEM ((2 * AS_FLOATS + 2 * BS_FLOATS) * sizeof(float))

__global__ __launch_bounds__(256)
void gemm_mma_kernel(const float* __restrict__ A, const float* __restrict__ W,
                     const float* __restrict__ bias, float* __restrict__ C,
                     int N, int K)
{
    extern __shared__ float smf[];
    float* As[2] = { smf, smf + AS_FLOATS };
    float* Bs[2] = { smf + 2 * AS_FLOATS, smf + 2 * AS_FLOATS + BS_FLOATS };

    const int t    = threadIdx.x;
    const int lane = t & 31;
    const int wid  = t >> 5;
    const int wm   = (wid >> 2) * 64;
    const int wn   = (wid & 3) * 32;
    const int g    = lane >> 2;
    const int t4   = lane & 3;
    const int m0   = blockIdx.y * 128;
    const int n0   = blockIdx.x * 128;

    float acc[4][4][4];
#pragma unroll
    for (int mi = 0; mi < 4; mi++)
#pragma unroll
        for (int ni = 0; ni < 4; ni++)
#pragma unroll
            for (int r = 0; r < 4; r++) acc[mi][ni][r] = 0.f;

    const int nch = K / 16;

    {
        const float* Ab = A + (size_t)m0 * K;
        const float* Wb = W + n0;
#pragma unroll
        for (int i = 0; i < 2; i++) {
            int idx = t + i * 256;
            int ar = idx >> 2, as = idx & 3;
            float4 v = *(const float4*)(Ab + (size_t)ar * K + as * 4);
            float* d = As[0] + ar * AS_P + as * 4;
            d[0] = f2tf32(v.x); d[1] = f2tf32(v.y); d[2] = f2tf32(v.z); d[3] = f2tf32(v.w);
            int br = idx >> 5, bs = idx & 31;
            float4 w = *(const float4*)(Wb + (size_t)br * N + bs * 4);
            float* e = Bs[0] + br * BS_P + bs * 4;
            e[0] = f2tf32(w.x); e[1] = f2tf32(w.y); e[2] = f2tf32(w.z); e[3] = f2tf32(w.w);
        }
    }
    __syncthreads();

    for (int ch = 0; ch < nch; ch++) {
        const int s = ch & 1;

        float4 ra[2], rb[2];
        if (ch + 1 < nch) {
            const float* Ab = A + (size_t)m0 * K + (ch + 1) * 16;
            const float* Wb = W + (size_t)(ch + 1) * 16 * N + n0;
#pragma unroll
            for (int i = 0; i < 2; i++) {
                int idx = t + i * 256;
                ra[i] = *(const float4*)(Ab + (size_t)(idx >> 2) * K + (idx & 3) * 4);
                rb[i] = *(const float4*)(Wb + (size_t)(idx >> 5) * N + (idx & 31) * 4);
            }
        }

        const float* as_ = As[s];
        const float* bs_ = Bs[s];
#pragma unroll
        for (int ks = 0; ks < 2; ks++) {
            const int kk = ks * 8;
            uint32_t af[4][4], bf[4][2];
#pragma unroll
            for (int mi = 0; mi < 4; mi++) {
                int r0 = wm + mi * 16 + g;
                af[mi][0] = __float_as_uint(as_[r0 * AS_P + kk + t4]);
                af[mi][1] = __float_as_uint(as_[(r0 + 8) * AS_P + kk + t4]);
                af[mi][2] = __float_as_uint(as_[r0 * AS_P + kk + t4 + 4]);
                af[mi][3] = __float_as_uint(as_[(r0 + 8) * AS_P + kk + t4 + 4]);
            }
#pragma unroll
            for (int ni = 0; ni < 4; ni++) {
                int cc = wn + ni * 8 + g;
                bf[ni][0] = __float_as_uint(bs_[(kk + t4) * BS_P + cc]);
                bf[ni][1] = __float_as_uint(bs_[(kk + t4 + 4) * BS_P + cc]);
            }
#pragma unroll
            for (int mi = 0; mi < 4; mi++)
#pragma unroll
                for (int ni = 0; ni < 4; ni++)
                    mma_tf32(acc[mi][ni], af[mi], bf[ni]);
        }

        if (ch + 1 < nch) {
            __syncthreads();
            const int sn = s ^ 1;
#pragma unroll
            for (int i = 0; i < 2; i++) {
                int idx = t + i * 256;
                int ar = idx >> 2, as = idx & 3;
                float* d = As[sn] + ar * AS_P + as * 4;
                d[0] = f2tf32(ra[i].x); d[1] = f2tf32(ra[i].y);
                d[2] = f2tf32(ra[i].z); d[3] = f2tf32(ra[i].w);
                int br = idx >> 5, bs = idx & 31;
                float* e = Bs[sn] + br * BS_P + bs * 4;
                e[0] = f2tf32(rb[i].x); e[1] = f2tf32(rb[i].y);
                e[2] = f2tf32(rb[i].z); e[3] = f2tf32(rb[i].w);
            }
            __syncthreads();
        }
    }

#pragma unroll
    for (int mi = 0; mi < 4; mi++) {
        int row = m0 + wm + mi * 16 + g;
#pragma unroll
        for (int ni = 0; ni < 4; ni++) {
            int col = n0 + wn + ni * 8 + 2 * t4;
            float2 bv = *(const float2*)(bias + col);
            float2 v0 = make_float2(acc[mi][ni][0] + bv.x, acc[mi][ni][1] + bv.y);
            float2 v1 = make_float2(acc[mi][ni][2] + bv.x, acc[mi][ni][3] + bv.y);
            *(float2*)(C + (size_t)row * N + col)       = v0;
            *(float2*)(C + (size_t)(row + 8) * N + col) = v1;
        }
    }
}

// ===========================================================================
// tf32 mma.sync flash attention.
// CTA: 256 threads (8 warps), 128 queries per CTA, K-tiles of 64 keys.
// Warp w owns score rows w*16..w*16+15 (full rows -> softmax is quad-local).
// Smem pitches = 68 floats: fragment patterns map to banks 4g+t4 (distinct).
// ===========================================================================
#define QS_OFF 0                    // [128][68]
#define KS_OFF (128*68)             // [64][68]
#define VT_OFF (KS_OFF + 64*68)     // [64][68]  Vt[d][key]
#define PS_OFF (VT_OFF + 64*68)     // 8 x [16][68]
#define ATT_SMEM_FLOATS (PS_OFF + 8*16*68)
#define ATT_SMEM (ATT_SMEM_FLOATS * sizeof(float))   // 104448 B

__global__ __launch_bounds__(256, 2)
void attn_mma_kernel(const float* __restrict__ qkv, const float* __restrict__ mask,
                     float* __restrict__ att)
{
    extern __shared__ float smf[];
    float* Qs = smf + QS_OFF;
    float* Ks = smf + KS_OFF;
    float* Vt = smf + VT_OFF;

    const int t    = threadIdx.x;
    const int lane = t & 31;
    const int wid  = t >> 5;
    const int g    = lane >> 2;
    const int t4   = lane & 3;
    const int bh   = blockIdx.y;
    const int b    = bh / HEADS;
    const int h    = bh % HEADS;
    const int q0   = blockIdx.x * 128;

    float* Ps = smf + PS_OFF + wid * (16 * 68);

    // ---- load Q tile [128][64], fold 1/8 scale, cvt tf32 ----
    {
        const float* qb = qkv + ((size_t)(b * SEQ + q0)) * QKV_N + h * (3 * HD);
#pragma unroll
        for (int i = 0; i < 8; i++) {
            int idx = t + i * 256;
            int row = idx >> 4, seg = idx & 15;
            float4 v = *(const float4*)(qb + (size_t)row * QKV_N + seg * 4);
            float* d = Qs + row * 68 + seg * 4;
            d[0] = f2tf32(v.x * 0.125f); d[1] = f2tf32(v.y * 0.125f);
            d[2] = f2tf32(v.z * 0.125f); d[3] = f2tf32(v.w * 0.125f);
        }
    }

    float m0 = -1e30f, m1 = -1e30f, l0 = 0.f, l1 = 0.f;
    float acc[8][4];
#pragma unroll
    for (int ni = 0; ni < 8; ni++)
#pragma unroll
        for (int r = 0; r < 4; r++) acc[ni][r] = 0.f;

    const int qrow = wid * 16 + g;
    const float* qsw = Qs + qrow * 68;           // warp's A rows (g / g+8 handled via +8*68)

    for (int kt = 0; kt < SEQ / 64; kt++) {
        const int k0 = kt * 64;
        __syncthreads();   // protect Ks/Vt from previous iteration readers

        // ---- K tile [64][64] -> Ks (tf32) ----
        {
            const float* kb = qkv + ((size_t)(b * SEQ + k0)) * QKV_N + h * (3 * HD) + HD;
#pragma unroll
            for (int i = 0; i < 4; i++) {
                int idx = t + i * 256;
                int row = idx >> 4, seg = idx & 15;
                float4 v = *(const float4*)(kb + (size_t)row * QKV_N + seg * 4);
                float* d = Ks + row * 68 + seg * 4;
                d[0] = f2tf32(v.x); d[1] = f2tf32(v.y); d[2] = f2tf32(v.z); d[3] = f2tf32(v.w);
            }
        }
        // ---- V tile [64][64] -> Vt[d][key] via 4x4 register micro-transpose ----
        {
            const int kg = t >> 4, ds = t & 15;
            const float* vb = qkv + ((size_t)(b * SEQ + k0 + kg * 4)) * QKV_N
                            + h * (3 * HD) + 2 * HD + ds * 4;
            float4 r0 = *(const float4*)(vb);
            float4 r1 = *(const float4*)(vb + QKV_N);
            float4 r2 = *(const float4*)(vb + 2 * QKV_N);
            float4 r3 = *(const float4*)(vb + 3 * QKV_N);
            float* d0 = Vt + (ds * 4 + 0) * 68 + kg * 4;
            float* d1 = Vt + (ds * 4 + 1) * 68 + kg * 4;
            float* d2 = Vt + (ds * 4 + 2) * 68 + kg * 4;
            float* d3 = Vt + (ds * 4 + 3) * 68 + kg * 4;
            *(float4*)d0 = make_float4(f2tf32(r0.x), f2tf32(r1.x), f2tf32(r2.x), f2tf32(r3.x));
            *(float4*)d1 = make_float4(f2tf32(r0.y), f2tf32(r1.y), f2tf32(r2.y), f2tf32(r3.y));
            *(float4*)d2 = make_float4(f2tf32(r0.z), f2tf32(r1.z), f2tf32(r2.z), f2tf32(r3.z));
            *(float4*)d3 = make_float4(f2tf32(r0.w), f2tf32(r1.w), f2tf32(r2.w), f2tf32(r3.w));
        }
        __syncthreads();

        // ---- scores = Q @ K^T  (16 x 64 per warp) ----
        float sc[8][4];
#pragma unroll
        for (int ni = 0; ni < 8; ni++)
#pragma unroll
            for (int r = 0; r < 4; r++) sc[ni][r] = 0.f;

#pragma unroll
        for (int kk = 0; kk < 64; kk += 8) {
            uint32_t af[4];
            af[0] = __float_as_uint(qsw[kk + t4]);
            af[1] = __float_as_uint(qsw[8 * 68 + kk + t4]);
            af[2] = __float_as_uint(qsw[kk + t4 + 4]);
            af[3] = __float_as_uint(qsw[8 * 68 + kk + t4 + 4]);
#pragma unroll
            for (int ni = 0; ni < 8; ni++) {
                uint32_t bf[2];
                bf[0] = __float_as_uint(Ks[(ni * 8 + g) * 68 + kk + t4]);
                bf[1] = __float_as_uint(Ks[(ni * 8 + g) * 68 + kk + t4 + 4]);
                mma_tf32(sc[ni], af, bf);
            }
        }

        // ---- + mask, online softmax (rows g and g+8) ----
        {
            const float* mr0 = mask + (size_t)(q0 + qrow) * SEQ + k0 + 2 * t4;
            const float* mr1 = mr0 + 8 * SEQ;
            float mx0 = -1e30f, mx1 = -1e30f;
#pragma unroll
            for (int ni = 0; ni < 8; ni++) {
                float2 a = *(const float2*)(mr0 + 8 * ni);
                float2 c = *(const float2*)(mr1 + 8 * ni);
                sc[ni][0] += a.x; sc[ni][1] += a.y;
                sc[ni][2] += c.x; sc[ni][3] += c.y;
                mx0 = fmaxf(mx0, fmaxf(sc[ni][0], sc[ni][1]));
                mx1 = fmaxf(mx1, fmaxf(sc[ni][2], sc[ni][3]));
            }
#pragma unroll
            for (int off = 1; off <= 2; off <<= 1) {
                mx0 = fmaxf(mx0, __shfl_xor_sync(0xffffffffu, mx0, off));
                mx1 = fmaxf(mx1, __shfl_xor_sync(0xffffffffu, mx1, off));
            }
            float mn0 = fmaxf(m0, mx0), mn1 = fmaxf(m1, mx1);
            float c0 = __expf(m0 - mn0), c1 = __expf(m1 - mn1);
            float rs0 = 0.f, rs1 = 0.f;
            float* p0 = Ps + g * 68 + 2 * t4;
            float* p1 = Ps + (g + 8) * 68 + 2 * t4;
#pragma unroll
            for (int ni = 0; ni < 8; ni++) {
                float e00 = f2tf32(__expf(sc[ni][0] - mn0));
                float e01 = f2tf32(__expf(sc[ni][1] - mn0));
                float e10 = f2tf32(__expf(sc[ni][2] - mn1));
                float e11 = f2tf32(__expf(sc[ni][3] - mn1));
                rs0 += e00 + e01; rs1 += e10 + e11;
                *(float2*)(p0 + 8 * ni) = make_float2(e00, e01);
                *(float2*)(p1 + 8 * ni) = make_float2(e10, e11);
            }
#pragma unroll
            for (int off = 1; off <= 2; off <<= 1) {
                rs0 += __shfl_xor_sync(0xffffffffu, rs0, off);
                rs1 += __shfl_xor_sync(0xffffffffu, rs1, off);
            }
            l0 = l0 * c0 + rs0; l1 = l1 * c1 + rs1;
            m0 = mn0; m1 = mn1;
#pragma unroll
            for (int ni = 0; ni < 8; ni++) {
                acc[ni][0] *= c0; acc[ni][1] *= c0;
                acc[ni][2] *= c1; acc[ni][3] *= c1;
            }
        }
        __syncwarp();

        // ---- acc += P @ V  (A = Ps, B = Vt) ----
#pragma unroll
        for (int kk = 0; kk < 64; kk += 8) {
            uint32_t af[4];
            af[0] = __float_as_uint(Ps[g * 68 + kk + t4]);
            af[1] = __float_as_uint(Ps[(g + 8) * 68 + kk + t4]);
            af[2] = __float_as_uint(Ps[g * 68 + kk + t4 + 4]);
            af[3] = __float_as_uint(Ps[(g + 8) * 68 + kk + t4 + 4]);
#pragma unroll
            for (int ni = 0; ni < 8; ni++) {
                uint32_t bf[2];
                bf[0] = __float_as_uint(Vt[(ni * 8 + g) * 68 + kk + t4]);
                bf[1] = __float_as_uint(Vt[(ni * 8 + g) * 68 + kk + t4 + 4]);
                mma_tf32(acc[ni], af, bf);
            }
        }
    }

    // ---- normalize + store: att[b*S + q][h*64 + d] ----
    {
        float inv0 = 1.f / l0, inv1 = 1.f / l1;
        float* o0 = att + (size_t)(b * SEQ + q0 + qrow) * DMODEL + h * HD + 2 * t4;
        float* o1 = o0 + 8 * DMODEL;
#pragma unroll
        for (int ni = 0; ni < 8; ni++) {
            *(float2*)(o0 + 8 * ni) = make_float2(acc[ni][0] * inv0, acc[ni][1] * inv0);
            *(float2*)(o1 + 8 * ni) = make_float2(acc[ni][2] * inv1, acc[ni][3] * inv1);
        }
    }
}

// ---------------------------------------------------------------------------
extern "C" void kernel_launch(void* const* d_in, const int* in_sizes, int n_in,
                              void* d_out, int out_size)
{
    const float* x     = (const float*)d_in[0];
    const float* mask  = (const float*)d_in[1];
    const float* w_qkv = (const float*)d_in[2];
    const float* b_qkv = (const float*)d_in[3];
    const float* w_out = (const float*)d_in[4];
    const float* b_out = (const float*)d_in[5];
    float* out = (float*)d_out;

    float* qkv; cudaGetSymbolAddress((void**)&qkv, g_qkv);
    float* att; cudaGetSymbolAddress((void**)&att, g_att);

    cudaFuncSetAttribute(gemm_mma_kernel, cudaFuncAttributeMaxDynamicSharedMemorySize,
                         (int)GEMM_SMEM);
    cudaFuncSetAttribute(attn_mma_kernel, cudaFuncAttributeMaxDynamicSharedMemorySize,
                         (int)ATT_SMEM);

    // 1) QKV projection (tf32 mma)
    {
        dim3 grid(QKV_N / 128, MROWS / 128);
        gemm_mma_kernel<<<grid, 256, GEMM_SMEM>>>(x, w_qkv, b_qkv, qkv, QKV_N, DMODEL);
    }
    // 2) attention (tf32 mma flash)
    {
        dim3 grid(SEQ / 128, BATCH * HEADS);
        attn_mma_kernel<<<grid, 256, ATT_SMEM>>>(qkv, mask, att);
    }
    // 3) output projection (tf32 mma)
    {
        dim3 grid(DMODEL / 128, MROWS / 128);
        gemm_mma_kernel<<<grid, 256, GEMM_SMEM>>>(att, w_out, b_out, out, DMODEL, DMODEL);
    }
}